// round 9
// baseline (speedup 1.0000x reference)
#include <cuda_runtime.h>
#include <cuda_bf16.h>
#include <cstdint>

#define NN 131072      // B*L nodes
#define LL 2048        // nodes per tree
#define HH 128         // hidden
#define LOG2L 11

// ---------------- scratch (device globals; no allocation allowed) ----------
__device__ float g_bufA[NN * HH];   // x_up
__device__ float g_bufB[NN * HH];   // layer cur / dotv buffer
__device__ float g_bufC[NN * HH];   // gemm out
__device__ float g_bufD[NN * HH];   // lin out
__device__ float g_pre[16];         // [0..11] w_e per up layer, [12]=W0·a_s, [13]=W0·a_d
__device__ __nv_bfloat16 g_wt[12 * 16384];  // 6 mats x {hi,lo} planes, transposed [n][k]

__device__ __forceinline__ float lrelu(float v) { return v > 0.f ? v : 0.2f * v; }
__device__ __forceinline__ float warpsum(float v) {
    #pragma unroll
    for (int o = 16; o; o >>= 1) v += __shfl_xor_sync(0xffffffffu, v, o);
    return v;
}
__device__ __forceinline__ float dot4(float4 a, float4 b) {
    return a.x * b.x + a.y * b.y + a.z * b.z + a.w * b.w;
}
__device__ __forceinline__ uint32_t smem_u32(const void* p) {
    uint32_t a;
    asm("{ .reg .u64 t; cvta.to.shared.u64 t, %1; cvt.u32.u64 %0, t; }" : "=r"(a) : "l"(p));
    return a;
}

// ======================= HMMA helpers (sm_80+ PTX) =========================
__device__ __forceinline__ void ldsm_x4(uint32_t* r, uint32_t addr) {
    asm volatile("ldmatrix.sync.aligned.m8n8.x4.shared.b16 {%0,%1,%2,%3}, [%4];"
                 : "=r"(r[0]), "=r"(r[1]), "=r"(r[2]), "=r"(r[3]) : "r"(addr));
}
__device__ __forceinline__ void mma16816(float* c, const uint32_t* a, const uint32_t* b) {
    asm volatile("mma.sync.aligned.m16n8k16.row.col.f32.bf16.bf16.f32 "
                 "{%0,%1,%2,%3}, {%4,%5,%6,%7}, {%8,%9}, {%0,%1,%2,%3};"
                 : "+f"(c[0]), "+f"(c[1]), "+f"(c[2]), "+f"(c[3])
                 : "r"(a[0]), "r"(a[1]), "r"(a[2]), "r"(a[3]), "r"(b[0]), "r"(b[1]));
}

// SMEM byte layout for GEMM (padded row stride = 136 halfs = 272 B)
#define A_HI 0
#define A_LO 17408
#define B_HI 34816
#define B_LO 69632
#define SMEM_GEMM 104448

// ---------------- weight pre-conversion: W[k][n] -> hi/lo bf16 [n][k] ------
__global__ void wconv_k(const float* __restrict__ up_W,
                        const float* __restrict__ down_W,
                        const float* __restrict__ lin_W) {
    int bx = blockIdx.x;
    int mat = bx >> 7, n = bx & 127, k = threadIdx.x;
    const float* W = (mat < 2) ? up_W + mat * 16384
                   : (mat < 4) ? down_W + (mat - 2) * 16384
                               : lin_W + (mat - 4) * 16384;
    float w = W[k * 128 + n];
    __nv_bfloat16 hb = __float2bfloat16(w);
    float hf = __bfloat162float(hb);
    g_wt[(mat * 2 + 0) * 16384 + n * 128 + k] = hb;
    g_wt[(mat * 2 + 1) * 16384 + n * 128 + k] = __float2bfloat16(w - hf);
}

// ============== HMMA GEMM: C[M,128] = f(A)[M,128] @ W[128,128] =============
// bf16 split: D = Ahi*Whi + Alo*Whi + Ahi*Wlo, 2-pass mainloop.
// 128 threads, CTA tile 64x128, 4 warps at 2Mx2N, warp tile 32x64
// (wider N per warp cuts smem bytes/output by 30% vs 32x32).
// If xup != nullptr: fused A-load  A[v] = relu(Ain[parent(v)] + dbias) + xup[v]
__global__ void __launch_bounds__(128, 2)
gemm_hmma(const float* __restrict__ A, const float* __restrict__ xup,
          const float* __restrict__ dbias,
          const __nv_bfloat16* __restrict__ Wt,
          float* __restrict__ C, const float* __restrict__ bias, int dorelu) {
    extern __shared__ char smem[];
    uint32_t sb = smem_u32(smem);
    int tid = threadIdx.x;

    // B planes: already transposed bf16 [n][k]; copy into padded smem
    const uint4* Bh = (const uint4*)Wt;
    const uint4* Bl = (const uint4*)(Wt + 16384);
    #pragma unroll
    for (int i = tid; i < 2048; i += 128) {
        int n = i >> 4, kq = i & 15;
        uint32_t off = n * 272 + kq * 16;
        *(uint4*)(smem + B_HI + off) = Bh[i];
        *(uint4*)(smem + B_LO + off) = Bl[i];
    }
    // A tile: 64 rows x 128 fp32 -> hi/lo bf16 planes (optionally fused gather)
    #pragma unroll
    for (int i = tid; i < 2048; i += 128) {
        int row = i >> 5, c4 = i & 31;
        float4 v;
        if (xup) {
            int vv = blockIdx.x * 64 + row;
            int l = vv & (LL - 1);
            float4 b4 = ((const float4*)dbias)[c4];
            float4 xu = ((const float4*)xup)[(size_t)vv * 32 + c4];
            if (l == 0) {
                v.x = fmaxf(b4.x, 0.f) + xu.x;
                v.y = fmaxf(b4.y, 0.f) + xu.y;
                v.z = fmaxf(b4.z, 0.f) + xu.z;
                v.w = fmaxf(b4.w, 0.f) + xu.w;
            } else {
                int p = vv - l + ((l - 1) >> 1);
                float4 cp = ((const float4*)A)[(size_t)p * 32 + c4];
                v.x = fmaxf(cp.x + b4.x, 0.f) + xu.x;
                v.y = fmaxf(cp.y + b4.y, 0.f) + xu.y;
                v.z = fmaxf(cp.z + b4.z, 0.f) + xu.z;
                v.w = fmaxf(cp.w + b4.w, 0.f) + xu.w;
            }
        } else {
            v = ((const float4*)(A + (size_t)blockIdx.x * 64 * 128))[i];
        }
        float f[4] = {v.x, v.y, v.z, v.w};
        union { uint2 u; __nv_bfloat16 h[4]; } ph, pl;
        #pragma unroll
        for (int e = 0; e < 4; e++) {
            __nv_bfloat16 hb = __float2bfloat16(f[e]);
            ph.h[e] = hb;
            pl.h[e] = __float2bfloat16(f[e] - __bfloat162float(hb));
        }
        uint32_t off = row * 272 + c4 * 8;
        *(uint2*)(smem + A_HI + off) = ph.u;
        *(uint2*)(smem + A_LO + off) = pl.u;
    }
    __syncthreads();

    int wid = tid >> 5, lane = tid & 31;
    int m0 = (wid & 1) * 32, n0 = (wid >> 1) * 64;
    float acc[2][8][4];
    #pragma unroll
    for (int a = 0; a < 2; a++)
        #pragma unroll
        for (int b = 0; b < 8; b++)
            #pragma unroll
            for (int c = 0; c < 4; c++) acc[a][b][c] = 0.f;

    int g = lane >> 3, r = lane & 7;
    uint32_t aoff0 = (uint32_t)((m0 + (g & 1) * 8 + r) * 272 + (g >> 1) * 16);
    // B x4: one load fills two adjacent n-fragments (8-row stride pair)
    uint32_t boff0 = (uint32_t)((n0 + (g >> 1) * 8 + r) * 272 + (g & 1) * 16);

    // ---- pass A: Bhi; both Ahi and Alo products ----
    #pragma unroll 4
    for (int k16 = 0; k16 < 8; k16++) {
        uint32_t ah[2][4], al[2][4], bh[8][2];
        ldsm_x4(ah[0], sb + A_HI + aoff0 + k16 * 32);
        ldsm_x4(ah[1], sb + A_HI + aoff0 + 16 * 272 + k16 * 32);
        ldsm_x4(al[0], sb + A_LO + aoff0 + k16 * 32);
        ldsm_x4(al[1], sb + A_LO + aoff0 + 16 * 272 + k16 * 32);
        #pragma unroll
        for (int p = 0; p < 4; p++)
            ldsm_x4(&bh[2 * p][0], sb + B_HI + boff0 + p * 16 * 272 + k16 * 32);
        #pragma unroll
        for (int mf = 0; mf < 2; mf++)
            #pragma unroll
            for (int nf = 0; nf < 8; nf++)
                mma16816(acc[mf][nf], ah[mf], bh[nf]);
        #pragma unroll
        for (int mf = 0; mf < 2; mf++)
            #pragma unroll
            for (int nf = 0; nf < 8; nf++)
                mma16816(acc[mf][nf], al[mf], bh[nf]);
    }
    // ---- pass B: Ahi * Blo ----
    #pragma unroll 4
    for (int k16 = 0; k16 < 8; k16++) {
        uint32_t ah[2][4], bl[8][2];
        ldsm_x4(ah[0], sb + A_HI + aoff0 + k16 * 32);
        ldsm_x4(ah[1], sb + A_HI + aoff0 + 16 * 272 + k16 * 32);
        #pragma unroll
        for (int p = 0; p < 4; p++)
            ldsm_x4(&bl[2 * p][0], sb + B_LO + boff0 + p * 16 * 272 + k16 * 32);
        #pragma unroll
        for (int mf = 0; mf < 2; mf++)
            #pragma unroll
            for (int nf = 0; nf < 8; nf++)
                mma16816(acc[mf][nf], ah[mf], bl[nf]);
    }

    // epilogue
    size_t rbase = (size_t)blockIdx.x * 64;
    int cr = lane >> 2, cc = (lane & 3) * 2;
    #pragma unroll
    for (int mf = 0; mf < 2; mf++) {
        #pragma unroll
        for (int nf = 0; nf < 8; nf++) {
            int col = n0 + nf * 8 + cc;
            float bx = bias ? bias[col] : 0.f;
            float by = bias ? bias[col + 1] : 0.f;
            int row0 = m0 + mf * 16 + cr;
            float2 v0 = {acc[mf][nf][0] + bx, acc[mf][nf][1] + by};
            float2 v1 = {acc[mf][nf][2] + bx, acc[mf][nf][3] + by};
            if (dorelu) {
                v0.x = fmaxf(v0.x, 0.f); v0.y = fmaxf(v0.y, 0.f);
                v1.x = fmaxf(v1.x, 0.f); v1.y = fmaxf(v1.y, 0.f);
            }
            *(float2*)(C + (rbase + row0) * 128 + col) = v0;
            *(float2*)(C + (rbase + row0 + 8) * 128 + col) = v1;
        }
    }
}

// ---------------- tiny precompute: w_e = We @ a_e per up layer, W0 dots ----
__global__ void precompute_k(const float* __restrict__ up_We,
                             const float* __restrict__ up_ae,
                             const float* __restrict__ up_W0,
                             const float* __restrict__ as0,
                             const float* __restrict__ ad0) {
    int lane = threadIdx.x;
    for (int i = 0; i < 3; i++) {
        for (int d = 0; d < 4; d++) {
            float s = 0.f;
            for (int t = lane; t < HH; t += 32)
                s += up_We[(i * 4 + d) * HH + t] * up_ae[i * HH + t];
            s = warpsum(s);
            if (lane == 0) g_pre[i * 4 + d] = s;
        }
    }
    float s = 0.f;
    for (int t = lane; t < HH; t += 32) s += up_W0[t] * as0[t];
    s = warpsum(s);
    if (lane == 0) g_pre[12] = s;
    s = 0.f;
    for (int t = lane; t < HH; t += 32) s += up_W0[t] * ad0[t];
    s = warpsum(s);
    if (lane == 0) g_pre[13] = s;
}

// ---------------- up layer 0: W0 is (1,H) -> scalar attn, warp per node ----
__global__ void up0_k(const float* __restrict__ x, const float* __restrict__ W0,
                      const float* __restrict__ bias,
                      const float* __restrict__ edge_attr,
                      float* __restrict__ out) {
    int w = threadIdx.x >> 5, lane = threadIdx.x & 31;
    int v = blockIdx.x * 8 + w;
    int l = v & (LL - 1), bi = v >> LOG2L;
    float xv = x[v];
    int nc = (l < 1023) ? 2 : ((l == 1023) ? 1 : 0);
    float comb;
    if (nc == 0) {
        comb = xv;
    } else {
        float was = g_pre[12], wad = g_pre[13];
        float we0 = g_pre[0], we1 = g_pre[1], we2 = g_pre[2], we3 = g_pre[3];
        int c1 = v + l + 1;
        float x1 = x[c1];
        float x2 = (nc == 2) ? x[c1 + 1] : 0.f;
        long e1 = (long)bi * 2047 + 2 * l;
        const float* ea1 = edge_attr + e1 * 4;
        float e1s = ea1[0] * we0 + ea1[1] * we1 + ea1[2] * we2 + ea1[3] * we3;
        float e2s = 0.f;
        if (nc == 2) {
            const float* ea2 = ea1 + 4;
            e2s = ea2[0] * we0 + ea2[1] * we1 + ea2[2] * we2 + ea2[3] * we3;
        }
        float adv = xv * wad;
        float s1 = lrelu(x1 * was + adv + e1s);
        float s2 = (nc == 2) ? lrelu(x2 * was + adv + e2s) : -1e30f;
        float emean = (nc == 2) ? 0.5f * (e1s + e2s) : e1s;
        float ss = lrelu(xv * was + adv + emean);
        float m = fmaxf(ss, fmaxf(s1, s2));
        float w1 = __expf(s1 - m);
        float w2 = (nc == 2) ? __expf(s2 - m) : 0.f;
        float ws = __expf(ss - m);
        comb = (w1 * x1 + w2 * x2 + ws * xv) / (w1 + w2 + ws);
    }
    float4 w0 = ((const float4*)W0)[lane];
    float4 b4 = ((const float4*)bias)[lane];
    float4 o;
    o.x = fmaxf(comb * w0.x + b4.x, 0.f);
    o.y = fmaxf(comb * w0.y + b4.y, 0.f);
    o.z = fmaxf(comb * w0.z + b4.z, 0.f);
    o.w = fmaxf(comb * w0.w + b4.w, 0.f);
    ((float4*)(out + (size_t)v * HH))[lane] = o;
}

// ---------------- up attention (standalone): warp per node -----------------
__global__ void up_attn_k(const float* __restrict__ h, const float* __restrict__ a_s,
                          const float* __restrict__ a_d,
                          const float* __restrict__ edge_attr, int layer,
                          const float* __restrict__ bias, float* __restrict__ out) {
    int w = threadIdx.x >> 5, lane = threadIdx.x & 31;
    int v = blockIdx.x * 8 + w;
    int l = v & (LL - 1), bi = v >> LOG2L;
    const float4* H = (const float4*)h;
    float4 hv = H[(size_t)v * 32 + lane];
    float4 b4 = ((const float4*)bias)[lane];
    int nc = (l < 1023) ? 2 : ((l == 1023) ? 1 : 0);
    float4* O = (float4*)(out + (size_t)v * HH);
    if (nc == 0) {
        float4 o;
        o.x = fmaxf(hv.x + b4.x, 0.f); o.y = fmaxf(hv.y + b4.y, 0.f);
        o.z = fmaxf(hv.z + b4.z, 0.f); o.w = fmaxf(hv.w + b4.w, 0.f);
        O[lane] = o;
        return;
    }
    int c1 = v + l + 1;
    float4 h1 = H[(size_t)c1 * 32 + lane];
    float4 h2 = (nc == 2) ? H[(size_t)(c1 + 1) * 32 + lane] : make_float4(0, 0, 0, 0);
    float4 as4 = ((const float4*)a_s)[lane];
    float4 ad4 = ((const float4*)a_d)[lane];
    float A1 = warpsum(dot4(h1, as4));
    float A2 = warpsum(dot4(h2, as4));
    float AV = warpsum(dot4(hv, as4));
    float DV = warpsum(dot4(hv, ad4));

    const float* we = g_pre + layer * 4;
    long e1 = (long)bi * 2047 + 2 * l;
    const float* ea1 = edge_attr + e1 * 4;
    float e1s = ea1[0] * we[0] + ea1[1] * we[1] + ea1[2] * we[2] + ea1[3] * we[3];
    float e2s = 0.f;
    if (nc == 2) {
        const float* ea2 = ea1 + 4;
        e2s = ea2[0] * we[0] + ea2[1] * we[1] + ea2[2] * we[2] + ea2[3] * we[3];
    }
    float s1 = lrelu(A1 + DV + e1s);
    float s2 = (nc == 2) ? lrelu(A2 + DV + e2s) : -1e30f;
    float emean = (nc == 2) ? 0.5f * (e1s + e2s) : e1s;
    float ss = lrelu(AV + DV + emean);
    float m = fmaxf(ss, fmaxf(s1, s2));
    float w1 = __expf(s1 - m);
    float w2 = (nc == 2) ? __expf(s2 - m) : 0.f;
    float ws = __expf(ss - m);
    float inv = 1.f / (w1 + w2 + ws);
    float4 o;
    o.x = fmaxf((w1 * h1.x + w2 * h2.x + ws * hv.x) * inv + b4.x, 0.f);
    o.y = fmaxf((w1 * h1.y + w2 * h2.y + ws * hv.y) * inv + b4.y, 0.f);
    o.z = fmaxf((w1 * h1.z + w2 * h2.z + ws * hv.z) * inv + b4.z, 0.f);
    o.w = fmaxf((w1 * h1.w + w2 * h2.w + ws * hv.w) * inv + b4.w, 0.f);
    O[lane] = o;
}

// ------- last down_attn fused with final dot: warp per node ---------------
__global__ void down_final_k(const float* __restrict__ h, const float* __restrict__ bias,
                             const float* __restrict__ x_up, const float* __restrict__ wlast,
                             float* __restrict__ emb, float* __restrict__ dotv) {
    int w = threadIdx.x >> 5, lane = threadIdx.x & 31;
    int v = blockIdx.x * 8 + w;
    int l = v & (LL - 1);
    float4 xu = ((const float4*)x_up)[(size_t)v * 32 + lane];
    float4 b4 = ((const float4*)bias)[lane];
    float4 val;
    if (l == 0) val = b4;
    else {
        int p = v - l + ((l - 1) >> 1);
        float4 hp = ((const float4*)h)[(size_t)p * 32 + lane];
        val.x = hp.x + b4.x; val.y = hp.y + b4.y;
        val.z = hp.z + b4.z; val.w = hp.w + b4.w;
    }
    float4 o;
    o.x = fmaxf(val.x, 0.f) + xu.x;
    o.y = fmaxf(val.y, 0.f) + xu.y;
    o.z = fmaxf(val.z, 0.f) + xu.z;
    o.w = fmaxf(val.w, 0.f) + xu.w;
    ((float4*)(emb + (size_t)v * HH))[lane] = o;
    float4 w4 = ((const float4*)wlast)[lane];
    float q = warpsum(dot4(o, w4));
    if (lane == 0) dotv[v] = q;
}

// ---------------- out[v] = dotv[v] - dotv[root(v)] -------------------------
__global__ void sub_k(const float* __restrict__ dotv, float* __restrict__ out) {
    int v = blockIdx.x * 256 + threadIdx.x;
    out[v] = dotv[v] - dotv[v & ~(LL - 1)];
}

// ---------------------------------------------------------------------------
extern "C" void kernel_launch(void* const* d_in, const int* in_sizes, int n_in,
                              void* d_out, int out_size) {
    const float* x         = (const float*)d_in[0];
    const float* edge_attr = (const float*)d_in[3];
    const float* up_W0     = (const float*)d_in[4];
    const float* up_W      = (const float*)d_in[5];
    const float* up_as     = (const float*)d_in[6];
    const float* up_ad     = (const float*)d_in[7];
    const float* up_We     = (const float*)d_in[8];
    const float* up_ae     = (const float*)d_in[9];
    const float* up_b      = (const float*)d_in[10];
    const float* down_W    = (const float*)d_in[11];
    const float* down_b    = (const float*)d_in[16];
    const float* lin_W     = (const float*)d_in[17];
    const float* lin_b     = (const float*)d_in[18];
    const float* lin_lW    = (const float*)d_in[19];

    float *bufA, *bufB, *bufC, *bufD;
    __nv_bfloat16* wt;
    cudaGetSymbolAddress((void**)&bufA, g_bufA);
    cudaGetSymbolAddress((void**)&bufB, g_bufB);
    cudaGetSymbolAddress((void**)&bufC, g_bufC);
    cudaGetSymbolAddress((void**)&bufD, g_bufD);
    cudaGetSymbolAddress((void**)&wt, g_wt);

    cudaFuncSetAttribute(gemm_hmma, cudaFuncAttributeMaxDynamicSharedMemorySize,
                         SMEM_GEMM);

    float* out = (float*)d_out;
    float* emb = out + NN;   // output tuple: (out[B*L], emb[B*L*H]) concatenated

    // mats: 0,1 = up_W[0..1]; 2,3 = down_W[0..1]; 4,5 = lin_W[0..1]
    #define WT(m) (wt + (m) * 2 * 16384)

    precompute_k<<<1, 32>>>(up_We, up_ae, up_W0, up_as, up_ad);
    wconv_k<<<768, 128>>>(up_W, down_W, lin_W);

    // --- up layer 0 (W0 is 1x128: fully scalar attention) ---
    up0_k<<<NN / 8, 256>>>(x, up_W0, up_b, edge_attr, bufB);

    // --- up layer 1 ---
    gemm_hmma<<<NN / 64, 128, SMEM_GEMM>>>(bufB, nullptr, nullptr, WT(0), bufC, nullptr, 0);
    up_attn_k<<<NN / 8, 256>>>(bufC, up_as + HH, up_ad + HH, edge_attr, 1, up_b + HH, bufB);

    // --- up layer 2 -> x_up (bufA) ---
    gemm_hmma<<<NN / 64, 128, SMEM_GEMM>>>(bufB, nullptr, nullptr, WT(1), bufC, nullptr, 0);
    up_attn_k<<<NN / 8, 256>>>(bufC, up_as + 2 * HH, up_ad + 2 * HH, edge_attr, 2,
                               up_b + 2 * HH, bufA);

    // --- down 0 GEMM: C0 = x_up @ down_W0 ---
    gemm_hmma<<<NN / 64, 128, SMEM_GEMM>>>(bufA, nullptr, nullptr, WT(2), bufC, nullptr, 0);

    // --- loop i=0: lin GEMM with fused down_attn A-load (xx never stored) ---
    gemm_hmma<<<NN / 64, 128, SMEM_GEMM>>>(bufC, bufA, down_b, WT(4), bufD, lin_b, 1);
    gemm_hmma<<<NN / 64, 128, SMEM_GEMM>>>(bufD, nullptr, nullptr, WT(2), bufC, nullptr, 0);

    // --- loop i=1: lin GEMM (fused) + down GEMM ---
    gemm_hmma<<<NN / 64, 128, SMEM_GEMM>>>(bufC, bufA, down_b, WT(5), bufD, lin_b + HH, 1);
    gemm_hmma<<<NN / 64, 128, SMEM_GEMM>>>(bufD, nullptr, nullptr, WT(3), bufC, nullptr, 0);

    // --- last down_attn fused with final dot (emb into d_out, dotv in bufB) ---
    down_final_k<<<NN / 8, 256>>>(bufC, down_b + HH, bufA, lin_lW, emb, bufB);

    // --- out[v] = dotv[v] - dotv[root] ---
    sub_k<<<NN / 256, 256>>>(bufB, out);
}

// round 10
// speedup vs baseline: 1.0733x; 1.0733x over previous
#include <cuda_runtime.h>
#include <cuda_bf16.h>
#include <cstdint>

#define NN 131072      // B*L nodes
#define LL 2048        // nodes per tree
#define HH 128         // hidden
#define LOG2L 11
#define GEMM_GRID 296  // 2 CTAs per SM x 148 SMs, persistent
#define NTILES 2048    // NN / 64

// ---------------- scratch (device globals; no allocation allowed) ----------
__device__ float g_bufA[NN * HH];   // x_up
__device__ float g_bufB[NN * HH];   // layer cur / dotv buffer
__device__ float g_bufC[NN * HH];   // gemm out
__device__ float g_bufD[NN * HH];   // lin out
__device__ float g_pre[16];         // [0..11] w_e per up layer, [12]=W0·a_s, [13]=W0·a_d
__device__ __nv_bfloat16 g_wt[12 * 16384];  // 6 mats x {hi,lo} planes, transposed [n][k]

__device__ __forceinline__ float lrelu(float v) { return v > 0.f ? v : 0.2f * v; }
__device__ __forceinline__ float warpsum(float v) {
    #pragma unroll
    for (int o = 16; o; o >>= 1) v += __shfl_xor_sync(0xffffffffu, v, o);
    return v;
}
__device__ __forceinline__ float dot4(float4 a, float4 b) {
    return a.x * b.x + a.y * b.y + a.z * b.z + a.w * b.w;
}
__device__ __forceinline__ uint32_t smem_u32(const void* p) {
    uint32_t a;
    asm("{ .reg .u64 t; cvta.to.shared.u64 t, %1; cvt.u32.u64 %0, t; }" : "=r"(a) : "l"(p));
    return a;
}

// ======================= HMMA helpers (sm_80+ PTX) =========================
__device__ __forceinline__ void ldsm_x4(uint32_t* r, uint32_t addr) {
    asm volatile("ldmatrix.sync.aligned.m8n8.x4.shared.b16 {%0,%1,%2,%3}, [%4];"
                 : "=r"(r[0]), "=r"(r[1]), "=r"(r[2]), "=r"(r[3]) : "r"(addr));
}
__device__ __forceinline__ void mma16816(float* c, const uint32_t* a, const uint32_t* b) {
    asm volatile("mma.sync.aligned.m16n8k16.row.col.f32.bf16.bf16.f32 "
                 "{%0,%1,%2,%3}, {%4,%5,%6,%7}, {%8,%9}, {%0,%1,%2,%3};"
                 : "+f"(c[0]), "+f"(c[1]), "+f"(c[2]), "+f"(c[3])
                 : "r"(a[0]), "r"(a[1]), "r"(a[2]), "r"(a[3]), "r"(b[0]), "r"(b[1]));
}

// SMEM byte layout for GEMM (padded row stride = 136 halfs = 272 B)
#define A_HI 0
#define A_LO 17408
#define B_HI 34816
#define B_LO 69632
#define SMEM_GEMM 104448

// ---------------- weight pre-conversion: W[k][n] -> hi/lo bf16 [n][k] ------
__global__ void wconv_k(const float* __restrict__ up_W,
                        const float* __restrict__ down_W,
                        const float* __restrict__ lin_W) {
    int bx = blockIdx.x;
    int mat = bx >> 7, n = bx & 127, k = threadIdx.x;
    const float* W = (mat < 2) ? up_W + mat * 16384
                   : (mat < 4) ? down_W + (mat - 2) * 16384
                               : lin_W + (mat - 4) * 16384;
    float w = W[k * 128 + n];
    __nv_bfloat16 hb = __float2bfloat16(w);
    float hf = __bfloat162float(hb);
    g_wt[(mat * 2 + 0) * 16384 + n * 128 + k] = hb;
    g_wt[(mat * 2 + 1) * 16384 + n * 128 + k] = __float2bfloat16(w - hf);
}

// ============== persistent HMMA GEMM: C = f(A) @ W, W loaded ONCE ==========
// bf16 split: D = Ahi*Whi + Alo*Whi + Ahi*Wlo, 2-pass mainloop (R8 structure).
// grid = GEMM_GRID persistent CTAs; each loops over M-tiles of 64 rows.
// If xup != nullptr: fused A-load  A[v] = relu(Ain[parent(v)] + dbias) + xup[v]
__global__ void __launch_bounds__(256, 2)
gemm_hmma(const float* __restrict__ A, const float* __restrict__ xup,
          const float* __restrict__ dbias,
          const __nv_bfloat16* __restrict__ Wt,
          float* __restrict__ C, const float* __restrict__ bias, int dorelu) {
    extern __shared__ char smem[];
    uint32_t sb = smem_u32(smem);
    int tid = threadIdx.x;

    // ---- B planes loaded ONCE per CTA (amortized over ~7 tiles) ----
    const uint4* Bh = (const uint4*)Wt;
    const uint4* Bl = (const uint4*)(Wt + 16384);
    #pragma unroll
    for (int i = tid; i < 2048; i += 256) {
        int n = i >> 4, kq = i & 15;
        uint32_t off = n * 272 + kq * 16;
        *(uint4*)(smem + B_HI + off) = Bh[i];
        *(uint4*)(smem + B_LO + off) = Bl[i];
    }

    int wid = tid >> 5, lane = tid & 31;
    int m0 = (wid & 1) * 32, n0 = (wid >> 1) * 32;
    int g = lane >> 3, r = lane & 7;
    uint32_t aoff0 = (uint32_t)((m0 + (g & 1) * 8 + r) * 272 + (g >> 1) * 16);
    uint32_t boff0 = (uint32_t)((n0 + (g >> 1) * 8 + r) * 272 + (g & 1) * 16);
    int cr = lane >> 2, cc = (lane & 3) * 2;

    for (int tile = blockIdx.x; tile < NTILES; tile += GEMM_GRID) {
        // ---- A tile: 64 rows x 128 fp32 -> hi/lo bf16 (optional fused gather)
        #pragma unroll
        for (int i = tid; i < 2048; i += 256) {
            int row = i >> 5, c4 = i & 31;
            float4 v;
            if (xup) {
                int vv = tile * 64 + row;
                int l = vv & (LL - 1);
                float4 b4 = ((const float4*)dbias)[c4];
                float4 xu = ((const float4*)xup)[(size_t)vv * 32 + c4];
                if (l == 0) {
                    v.x = fmaxf(b4.x, 0.f) + xu.x;
                    v.y = fmaxf(b4.y, 0.f) + xu.y;
                    v.z = fmaxf(b4.z, 0.f) + xu.z;
                    v.w = fmaxf(b4.w, 0.f) + xu.w;
                } else {
                    int p = vv - l + ((l - 1) >> 1);
                    float4 cp = ((const float4*)A)[(size_t)p * 32 + c4];
                    v.x = fmaxf(cp.x + b4.x, 0.f) + xu.x;
                    v.y = fmaxf(cp.y + b4.y, 0.f) + xu.y;
                    v.z = fmaxf(cp.z + b4.z, 0.f) + xu.z;
                    v.w = fmaxf(cp.w + b4.w, 0.f) + xu.w;
                }
            } else {
                v = ((const float4*)(A + (size_t)tile * 64 * 128))[i];
            }
            float f[4] = {v.x, v.y, v.z, v.w};
            union { uint2 u; __nv_bfloat16 h[4]; } ph, pl;
            #pragma unroll
            for (int e = 0; e < 4; e++) {
                __nv_bfloat16 hb = __float2bfloat16(f[e]);
                ph.h[e] = hb;
                pl.h[e] = __float2bfloat16(f[e] - __bfloat162float(hb));
            }
            uint32_t off = row * 272 + c4 * 8;
            *(uint2*)(smem + A_HI + off) = ph.u;
            *(uint2*)(smem + A_LO + off) = pl.u;
        }
        __syncthreads();   // A (and on first iter, B) visible to all warps

        float acc[2][4][4];
        #pragma unroll
        for (int a = 0; a < 2; a++)
            #pragma unroll
            for (int b = 0; b < 4; b++)
                #pragma unroll
                for (int c = 0; c < 4; c++) acc[a][b][c] = 0.f;

        // ---- pass A: Bhi; both Ahi and Alo products ----
        #pragma unroll 4
        for (int k16 = 0; k16 < 8; k16++) {
            uint32_t ah[2][4], al[2][4], bh[4][2];
            ldsm_x4(ah[0], sb + A_HI + aoff0 + k16 * 32);
            ldsm_x4(ah[1], sb + A_HI + aoff0 + 16 * 272 + k16 * 32);
            ldsm_x4(al[0], sb + A_LO + aoff0 + k16 * 32);
            ldsm_x4(al[1], sb + A_LO + aoff0 + 16 * 272 + k16 * 32);
            ldsm_x4(&bh[0][0], sb + B_HI + boff0 + k16 * 32);
            ldsm_x4(&bh[2][0], sb + B_HI + boff0 + 16 * 272 + k16 * 32);
            #pragma unroll
            for (int mf = 0; mf < 2; mf++)
                #pragma unroll
                for (int nf = 0; nf < 4; nf++)
                    mma16816(acc[mf][nf], ah[mf], bh[nf]);
            #pragma unroll
            for (int mf = 0; mf < 2; mf++)
                #pragma unroll
                for (int nf = 0; nf < 4; nf++)
                    mma16816(acc[mf][nf], al[mf], bh[nf]);
        }
        // ---- pass B: Ahi * Blo ----
        #pragma unroll 4
        for (int k16 = 0; k16 < 8; k16++) {
            uint32_t ah[2][4], bl[4][2];
            ldsm_x4(ah[0], sb + A_HI + aoff0 + k16 * 32);
            ldsm_x4(ah[1], sb + A_HI + aoff0 + 16 * 272 + k16 * 32);
            ldsm_x4(&bl[0][0], sb + B_LO + boff0 + k16 * 32);
            ldsm_x4(&bl[2][0], sb + B_LO + boff0 + 16 * 272 + k16 * 32);
            #pragma unroll
            for (int mf = 0; mf < 2; mf++)
                #pragma unroll
                for (int nf = 0; nf < 4; nf++)
                    mma16816(acc[mf][nf], ah[mf], bl[nf]);
        }

        // ---- epilogue ----
        size_t rbase = (size_t)tile * 64;
        #pragma unroll
        for (int mf = 0; mf < 2; mf++) {
            #pragma unroll
            for (int nf = 0; nf < 4; nf++) {
                int col = n0 + nf * 8 + cc;
                float bx = bias ? bias[col] : 0.f;
                float by = bias ? bias[col + 1] : 0.f;
                int row0 = m0 + mf * 16 + cr;
                float2 v0 = {acc[mf][nf][0] + bx, acc[mf][nf][1] + by};
                float2 v1 = {acc[mf][nf][2] + bx, acc[mf][nf][3] + by};
                if (dorelu) {
                    v0.x = fmaxf(v0.x, 0.f); v0.y = fmaxf(v0.y, 0.f);
                    v1.x = fmaxf(v1.x, 0.f); v1.y = fmaxf(v1.y, 0.f);
                }
                *(float2*)(C + (rbase + row0) * 128 + col) = v0;
                *(float2*)(C + (rbase + row0 + 8) * 128 + col) = v1;
            }
        }
        __syncthreads();   // all warps done with A smem before next overwrite
    }
}

// ---------------- tiny precompute: w_e = We @ a_e per up layer, W0 dots ----
__global__ void precompute_k(const float* __restrict__ up_We,
                             const float* __restrict__ up_ae,
                             const float* __restrict__ up_W0,
                             const float* __restrict__ as0,
                             const float* __restrict__ ad0) {
    int lane = threadIdx.x;
    for (int i = 0; i < 3; i++) {
        for (int d = 0; d < 4; d++) {
            float s = 0.f;
            for (int t = lane; t < HH; t += 32)
                s += up_We[(i * 4 + d) * HH + t] * up_ae[i * HH + t];
            s = warpsum(s);
            if (lane == 0) g_pre[i * 4 + d] = s;
        }
    }
    float s = 0.f;
    for (int t = lane; t < HH; t += 32) s += up_W0[t] * as0[t];
    s = warpsum(s);
    if (lane == 0) g_pre[12] = s;
    s = 0.f;
    for (int t = lane; t < HH; t += 32) s += up_W0[t] * ad0[t];
    s = warpsum(s);
    if (lane == 0) g_pre[13] = s;
}

// ---------------- up layer 0: W0 is (1,H) -> scalar attn, warp per node ----
__global__ void up0_k(const float* __restrict__ x, const float* __restrict__ W0,
                      const float* __restrict__ bias,
                      const float* __restrict__ edge_attr,
                      float* __restrict__ out) {
    int w = threadIdx.x >> 5, lane = threadIdx.x & 31;
    int v = blockIdx.x * 8 + w;
    int l = v & (LL - 1), bi = v >> LOG2L;
    float xv = x[v];
    int nc = (l < 1023) ? 2 : ((l == 1023) ? 1 : 0);
    float comb;
    if (nc == 0) {
        comb = xv;
    } else {
        float was = g_pre[12], wad = g_pre[13];
        float we0 = g_pre[0], we1 = g_pre[1], we2 = g_pre[2], we3 = g_pre[3];
        int c1 = v + l + 1;
        float x1 = x[c1];
        float x2 = (nc == 2) ? x[c1 + 1] : 0.f;
        long e1 = (long)bi * 2047 + 2 * l;
        const float* ea1 = edge_attr + e1 * 4;
        float e1s = ea1[0] * we0 + ea1[1] * we1 + ea1[2] * we2 + ea1[3] * we3;
        float e2s = 0.f;
        if (nc == 2) {
            const float* ea2 = ea1 + 4;
            e2s = ea2[0] * we0 + ea2[1] * we1 + ea2[2] * we2 + ea2[3] * we3;
        }
        float adv = xv * wad;
        float s1 = lrelu(x1 * was + adv + e1s);
        float s2 = (nc == 2) ? lrelu(x2 * was + adv + e2s) : -1e30f;
        float emean = (nc == 2) ? 0.5f * (e1s + e2s) : e1s;
        float ss = lrelu(xv * was + adv + emean);
        float m = fmaxf(ss, fmaxf(s1, s2));
        float w1 = __expf(s1 - m);
        float w2 = (nc == 2) ? __expf(s2 - m) : 0.f;
        float ws = __expf(ss - m);
        comb = (w1 * x1 + w2 * x2 + ws * xv) / (w1 + w2 + ws);
    }
    float4 w0 = ((const float4*)W0)[lane];
    float4 b4 = ((const float4*)bias)[lane];
    float4 o;
    o.x = fmaxf(comb * w0.x + b4.x, 0.f);
    o.y = fmaxf(comb * w0.y + b4.y, 0.f);
    o.z = fmaxf(comb * w0.z + b4.z, 0.f);
    o.w = fmaxf(comb * w0.w + b4.w, 0.f);
    ((float4*)(out + (size_t)v * HH))[lane] = o;
}

// ---------------- up attention (standalone): warp per node -----------------
__global__ void up_attn_k(const float* __restrict__ h, const float* __restrict__ a_s,
                          const float* __restrict__ a_d,
                          const float* __restrict__ edge_attr, int layer,
                          const float* __restrict__ bias, float* __restrict__ out) {
    int w = threadIdx.x >> 5, lane = threadIdx.x & 31;
    int v = blockIdx.x * 8 + w;
    int l = v & (LL - 1), bi = v >> LOG2L;
    const float4* H = (const float4*)h;
    float4 hv = H[(size_t)v * 32 + lane];
    float4 b4 = ((const float4*)bias)[lane];
    int nc = (l < 1023) ? 2 : ((l == 1023) ? 1 : 0);
    float4* O = (float4*)(out + (size_t)v * HH);
    if (nc == 0) {
        float4 o;
        o.x = fmaxf(hv.x + b4.x, 0.f); o.y = fmaxf(hv.y + b4.y, 0.f);
        o.z = fmaxf(hv.z + b4.z, 0.f); o.w = fmaxf(hv.w + b4.w, 0.f);
        O[lane] = o;
        return;
    }
    int c1 = v + l + 1;
    float4 h1 = H[(size_t)c1 * 32 + lane];
    float4 h2 = (nc == 2) ? H[(size_t)(c1 + 1) * 32 + lane] : make_float4(0, 0, 0, 0);
    float4 as4 = ((const float4*)a_s)[lane];
    float4 ad4 = ((const float4*)a_d)[lane];
    float A1 = warpsum(dot4(h1, as4));
    float A2 = warpsum(dot4(h2, as4));
    float AV = warpsum(dot4(hv, as4));
    float DV = warpsum(dot4(hv, ad4));

    const float* we = g_pre + layer * 4;
    long e1 = (long)bi * 2047 + 2 * l;
    const float* ea1 = edge_attr + e1 * 4;
    float e1s = ea1[0] * we[0] + ea1[1] * we[1] + ea1[2] * we[2] + ea1[3] * we[3];
    float e2s = 0.f;
    if (nc == 2) {
        const float* ea2 = ea1 + 4;
        e2s = ea2[0] * we[0] + ea2[1] * we[1] + ea2[2] * we[2] + ea2[3] * we[3];
    }
    float s1 = lrelu(A1 + DV + e1s);
    float s2 = (nc == 2) ? lrelu(A2 + DV + e2s) : -1e30f;
    float emean = (nc == 2) ? 0.5f * (e1s + e2s) : e1s;
    float ss = lrelu(AV + DV + emean);
    float m = fmaxf(ss, fmaxf(s1, s2));
    float w1 = __expf(s1 - m);
    float w2 = (nc == 2) ? __expf(s2 - m) : 0.f;
    float ws = __expf(ss - m);
    float inv = 1.f / (w1 + w2 + ws);
    float4 o;
    o.x = fmaxf((w1 * h1.x + w2 * h2.x + ws * hv.x) * inv + b4.x, 0.f);
    o.y = fmaxf((w1 * h1.y + w2 * h2.y + ws * hv.y) * inv + b4.y, 0.f);
    o.z = fmaxf((w1 * h1.z + w2 * h2.z + ws * hv.z) * inv + b4.z, 0.f);
    o.w = fmaxf((w1 * h1.w + w2 * h2.w + ws * hv.w) * inv + b4.w, 0.f);
    O[lane] = o;
}

// ------- last down_attn fused with final dot: warp per node ---------------
__global__ void down_final_k(const float* __restrict__ h, const float* __restrict__ bias,
                             const float* __restrict__ x_up, const float* __restrict__ wlast,
                             float* __restrict__ emb, float* __restrict__ dotv) {
    int w = threadIdx.x >> 5, lane = threadIdx.x & 31;
    int v = blockIdx.x * 8 + w;
    int l = v & (LL - 1);
    float4 xu = ((const float4*)x_up)[(size_t)v * 32 + lane];
    float4 b4 = ((const float4*)bias)[lane];
    float4 val;
    if (l == 0) val = b4;
    else {
        int p = v - l + ((l - 1) >> 1);
        float4 hp = ((const float4*)h)[(size_t)p * 32 + lane];
        val.x = hp.x + b4.x; val.y = hp.y + b4.y;
        val.z = hp.z + b4.z; val.w = hp.w + b4.w;
    }
    float4 o;
    o.x = fmaxf(val.x, 0.f) + xu.x;
    o.y = fmaxf(val.y, 0.f) + xu.y;
    o.z = fmaxf(val.z, 0.f) + xu.z;
    o.w = fmaxf(val.w, 0.f) + xu.w;
    ((float4*)(emb + (size_t)v * HH))[lane] = o;
    float4 w4 = ((const float4*)wlast)[lane];
    float q = warpsum(dot4(o, w4));
    if (lane == 0) dotv[v] = q;
}

// ---------------- out[v] = dotv[v] - dotv[root(v)] -------------------------
__global__ void sub_k(const float* __restrict__ dotv, float* __restrict__ out) {
    int v = blockIdx.x * 256 + threadIdx.x;
    out[v] = dotv[v] - dotv[v & ~(LL - 1)];
}

// ---------------------------------------------------------------------------
extern "C" void kernel_launch(void* const* d_in, const int* in_sizes, int n_in,
                              void* d_out, int out_size) {
    const float* x         = (const float*)d_in[0];
    const float* edge_attr = (const float*)d_in[3];
    const float* up_W0     = (const float*)d_in[4];
    const float* up_W      = (const float*)d_in[5];
    const float* up_as     = (const float*)d_in[6];
    const float* up_ad     = (const float*)d_in[7];
    const float* up_We     = (const float*)d_in[8];
    const float* up_ae     = (const float*)d_in[9];
    const float* up_b      = (const float*)d_in[10];
    const float* down_W    = (const float*)d_in[11];
    const float* down_b    = (const float*)d_in[16];
    const float* lin_W     = (const float*)d_in[17];
    const float* lin_b     = (const float*)d_in[18];
    const float* lin_lW    = (const float*)d_in[19];

    float *bufA, *bufB, *bufC, *bufD;
    __nv_bfloat16* wt;
    cudaGetSymbolAddress((void**)&bufA, g_bufA);
    cudaGetSymbolAddress((void**)&bufB, g_bufB);
    cudaGetSymbolAddress((void**)&bufC, g_bufC);
    cudaGetSymbolAddress((void**)&bufD, g_bufD);
    cudaGetSymbolAddress((void**)&wt, g_wt);

    cudaFuncSetAttribute(gemm_hmma, cudaFuncAttributeMaxDynamicSharedMemorySize,
                         SMEM_GEMM);

    float* out = (float*)d_out;
    float* emb = out + NN;   // output tuple: (out[B*L], emb[B*L*H]) concatenated

    // mats: 0,1 = up_W[0..1]; 2,3 = down_W[0..1]; 4,5 = lin_W[0..1]
    #define WT(m) (wt + (m) * 2 * 16384)

    precompute_k<<<1, 32>>>(up_We, up_ae, up_W0, up_as, up_ad);
    wconv_k<<<768, 128>>>(up_W, down_W, lin_W);

    // --- up layer 0 (W0 is 1x128: fully scalar attention) ---
    up0_k<<<NN / 8, 256>>>(x, up_W0, up_b, edge_attr, bufB);

    // --- up layer 1 ---
    gemm_hmma<<<GEMM_GRID, 256, SMEM_GEMM>>>(bufB, nullptr, nullptr, WT(0), bufC, nullptr, 0);
    up_attn_k<<<NN / 8, 256>>>(bufC, up_as + HH, up_ad + HH, edge_attr, 1, up_b + HH, bufB);

    // --- up layer 2 -> x_up (bufA) ---
    gemm_hmma<<<GEMM_GRID, 256, SMEM_GEMM>>>(bufB, nullptr, nullptr, WT(1), bufC, nullptr, 0);
    up_attn_k<<<NN / 8, 256>>>(bufC, up_as + 2 * HH, up_ad + 2 * HH, edge_attr, 2,
                               up_b + 2 * HH, bufA);

    // --- down 0 GEMM: C0 = x_up @ down_W0 ---
    gemm_hmma<<<GEMM_GRID, 256, SMEM_GEMM>>>(bufA, nullptr, nullptr, WT(2), bufC, nullptr, 0);

    // --- loop i=0: lin GEMM with fused down_attn A-load (xx never stored) ---
    gemm_hmma<<<GEMM_GRID, 256, SMEM_GEMM>>>(bufC, bufA, down_b, WT(4), bufD, lin_b, 1);
    gemm_hmma<<<GEMM_GRID, 256, SMEM_GEMM>>>(bufD, nullptr, nullptr, WT(2), bufC, nullptr, 0);

    // --- loop i=1: lin GEMM (fused) + down GEMM ---
    gemm_hmma<<<GEMM_GRID, 256, SMEM_GEMM>>>(bufC, bufA, down_b, WT(5), bufD, lin_b + HH, 1);
    gemm_hmma<<<GEMM_GRID, 256, SMEM_GEMM>>>(bufD, nullptr, nullptr, WT(3), bufC, nullptr, 0);

    // --- last down_attn fused with final dot (emb into d_out, dotv in bufB) ---
    down_final_k<<<NN / 8, 256>>>(bufC, down_b + HH, bufA, lin_lW, emb, bufB);

    // --- out[v] = dotv[v] - dotv[root] ---
    sub_k<<<NN / 256, 256>>>(bufB, out);
}

// round 11
// speedup vs baseline: 1.1653x; 1.0857x over previous
#include <cuda_runtime.h>
#include <cuda_bf16.h>
#include <cstdint>

#define NN 131072      // B*L nodes
#define LL 2048        // nodes per tree
#define HH 128         // hidden
#define LOG2L 11
#define GEMM_GRID 296  // 2 CTAs per SM x 148 SMs, persistent
#define NTILES 2048    // NN / 64
#define FTILES 1024    // NN / 128 (fused kernel, 128-row tiles)
#define FGRID 148

// ---------------- scratch (device globals; no allocation allowed) ----------
__device__ float g_bufA[NN * HH];   // x_up
__device__ float g_bufB[NN * HH];   // layer cur / dotv buffer
__device__ float g_bufC[NN * HH];   // gemm out
__device__ float g_bufD[NN * HH];   // fused chain ping-pong
__device__ float g_pre[16];         // [0..11] w_e per up layer, [12]=W0·a_s, [13]=W0·a_d
__device__ __nv_bfloat16 g_wt[12 * 16384];  // 6 mats x {hi,lo} planes, transposed [n][k]

__device__ __forceinline__ float lrelu(float v) { return v > 0.f ? v : 0.2f * v; }
__device__ __forceinline__ float warpsum(float v) {
    #pragma unroll
    for (int o = 16; o; o >>= 1) v += __shfl_xor_sync(0xffffffffu, v, o);
    return v;
}
__device__ __forceinline__ float dot4(float4 a, float4 b) {
    return a.x * b.x + a.y * b.y + a.z * b.z + a.w * b.w;
}
__device__ __forceinline__ uint32_t smem_u32(const void* p) {
    uint32_t a;
    asm("{ .reg .u64 t; cvta.to.shared.u64 t, %1; cvt.u32.u64 %0, t; }" : "=r"(a) : "l"(p));
    return a;
}

// ======================= HMMA helpers (sm_80+ PTX) =========================
__device__ __forceinline__ void ldsm_x4(uint32_t* r, uint32_t addr) {
    asm volatile("ldmatrix.sync.aligned.m8n8.x4.shared.b16 {%0,%1,%2,%3}, [%4];"
                 : "=r"(r[0]), "=r"(r[1]), "=r"(r[2]), "=r"(r[3]) : "r"(addr));
}
__device__ __forceinline__ void mma16816(float* c, const uint32_t* a, const uint32_t* b) {
    asm volatile("mma.sync.aligned.m16n8k16.row.col.f32.bf16.bf16.f32 "
                 "{%0,%1,%2,%3}, {%4,%5,%6,%7}, {%8,%9}, {%0,%1,%2,%3};"
                 : "+f"(c[0]), "+f"(c[1]), "+f"(c[2]), "+f"(c[3])
                 : "r"(a[0]), "r"(a[1]), "r"(a[2]), "r"(a[3]), "r"(b[0]), "r"(b[1]));
}

// SMEM layout, plain GEMM (row stride 272 B)
#define A_HI 0
#define A_LO 17408
#define B_HI 34816
#define B_LO 69632
#define SMEM_GEMM 104448
// SMEM layout, fused kernel (128-row A, two B matrices)
#define FA_HI 0
#define FA_LO 34816
#define FB1_HI 69632
#define FB1_LO 104448
#define FB2_HI 139264
#define FB2_LO 174080
#define SMEM_FUSED 208896

// ---------------- weight pre-conversion: W[k][n] -> hi/lo bf16 [n][k] ------
__global__ void wconv_k(const float* __restrict__ up_W,
                        const float* __restrict__ down_W,
                        const float* __restrict__ lin_W) {
    int bx = blockIdx.x;
    int mat = bx >> 7, n = bx & 127, k = threadIdx.x;
    const float* W = (mat < 2) ? up_W + mat * 16384
                   : (mat < 4) ? down_W + (mat - 2) * 16384
                               : lin_W + (mat - 4) * 16384;
    float w = W[k * 128 + n];
    __nv_bfloat16 hb = __float2bfloat16(w);
    float hf = __bfloat162float(hb);
    g_wt[(mat * 2 + 0) * 16384 + n * 128 + k] = hb;
    g_wt[(mat * 2 + 1) * 16384 + n * 128 + k] = __float2bfloat16(w - hf);
}

// ============== persistent HMMA GEMM (R10): C = A @ W, W loaded ONCE =======
__global__ void __launch_bounds__(256, 2)
gemm_hmma(const float* __restrict__ A,
          const __nv_bfloat16* __restrict__ Wt,
          float* __restrict__ C) {
    extern __shared__ char smem[];
    uint32_t sb = smem_u32(smem);
    int tid = threadIdx.x;

    const uint4* Bh = (const uint4*)Wt;
    const uint4* Bl = (const uint4*)(Wt + 16384);
    #pragma unroll
    for (int i = tid; i < 2048; i += 256) {
        int n = i >> 4, kq = i & 15;
        uint32_t off = n * 272 + kq * 16;
        *(uint4*)(smem + B_HI + off) = Bh[i];
        *(uint4*)(smem + B_LO + off) = Bl[i];
    }

    int wid = tid >> 5, lane = tid & 31;
    int m0 = (wid & 1) * 32, n0 = (wid >> 1) * 32;
    int g = lane >> 3, r = lane & 7;
    uint32_t aoff0 = (uint32_t)((m0 + (g & 1) * 8 + r) * 272 + (g >> 1) * 16);
    uint32_t boff0 = (uint32_t)((n0 + (g >> 1) * 8 + r) * 272 + (g & 1) * 16);
    int cr = lane >> 2, cc = (lane & 3) * 2;

    for (int tile = blockIdx.x; tile < NTILES; tile += GEMM_GRID) {
        #pragma unroll
        for (int i = tid; i < 2048; i += 256) {
            int row = i >> 5, c4 = i & 31;
            float4 v = ((const float4*)(A + (size_t)tile * 64 * 128))[i];
            float f[4] = {v.x, v.y, v.z, v.w};
            union { uint2 u; __nv_bfloat16 h[4]; } ph, pl;
            #pragma unroll
            for (int e = 0; e < 4; e++) {
                __nv_bfloat16 hb = __float2bfloat16(f[e]);
                ph.h[e] = hb;
                pl.h[e] = __float2bfloat16(f[e] - __bfloat162float(hb));
            }
            uint32_t off = row * 272 + c4 * 8;
            *(uint2*)(smem + A_HI + off) = ph.u;
            *(uint2*)(smem + A_LO + off) = pl.u;
        }
        __syncthreads();

        float acc[2][4][4];
        #pragma unroll
        for (int a = 0; a < 2; a++)
            #pragma unroll
            for (int b = 0; b < 4; b++)
                #pragma unroll
                for (int c = 0; c < 4; c++) acc[a][b][c] = 0.f;

        #pragma unroll 4
        for (int k16 = 0; k16 < 8; k16++) {
            uint32_t ah[2][4], al[2][4], bh[4][2];
            ldsm_x4(ah[0], sb + A_HI + aoff0 + k16 * 32);
            ldsm_x4(ah[1], sb + A_HI + aoff0 + 16 * 272 + k16 * 32);
            ldsm_x4(al[0], sb + A_LO + aoff0 + k16 * 32);
            ldsm_x4(al[1], sb + A_LO + aoff0 + 16 * 272 + k16 * 32);
            ldsm_x4(&bh[0][0], sb + B_HI + boff0 + k16 * 32);
            ldsm_x4(&bh[2][0], sb + B_HI + boff0 + 16 * 272 + k16 * 32);
            #pragma unroll
            for (int mf = 0; mf < 2; mf++)
                #pragma unroll
                for (int nf = 0; nf < 4; nf++)
                    mma16816(acc[mf][nf], ah[mf], bh[nf]);
            #pragma unroll
            for (int mf = 0; mf < 2; mf++)
                #pragma unroll
                for (int nf = 0; nf < 4; nf++)
                    mma16816(acc[mf][nf], al[mf], bh[nf]);
        }
        #pragma unroll 4
        for (int k16 = 0; k16 < 8; k16++) {
            uint32_t ah[2][4], bl[4][2];
            ldsm_x4(ah[0], sb + A_HI + aoff0 + k16 * 32);
            ldsm_x4(ah[1], sb + A_HI + aoff0 + 16 * 272 + k16 * 32);
            ldsm_x4(&bl[0][0], sb + B_LO + boff0 + k16 * 32);
            ldsm_x4(&bl[2][0], sb + B_LO + boff0 + 16 * 272 + k16 * 32);
            #pragma unroll
            for (int mf = 0; mf < 2; mf++)
                #pragma unroll
                for (int nf = 0; nf < 4; nf++)
                    mma16816(acc[mf][nf], ah[mf], bl[nf]);
        }

        size_t rbase = (size_t)tile * 64;
        #pragma unroll
        for (int mf = 0; mf < 2; mf++) {
            #pragma unroll
            for (int nf = 0; nf < 4; nf++) {
                int col = n0 + nf * 8 + cc;
                int row0 = m0 + mf * 16 + cr;
                *(float2*)(C + (rbase + row0) * 128 + col) =
                    make_float2(acc[mf][nf][0], acc[mf][nf][1]);
                *(float2*)(C + (rbase + row0 + 8) * 128 + col) =
                    make_float2(acc[mf][nf][2], acc[mf][nf][3]);
            }
        }
        __syncthreads();
    }
}

// ====== fused lin+down chain: out = relu(gather(gC)+xup chain) @W1 relu @W2 =
// Per 128-row tile:
//   A[v] = relu(gC[parent(v)] + dbias) + xup[v]        (down_attn gather)
//   T    = relu(A @ W1 + lbias)       (lin layer; stays in smem, never global)
//   out  = T @ W2                     (down GEMM pre-activation)
// 512 threads, 1 CTA/SM, both weight matrices resident in smem.
__global__ void __launch_bounds__(512, 1)
gemm_fused2(const float* __restrict__ gC, const float* __restrict__ xup,
            const float* __restrict__ dbias,
            const __nv_bfloat16* __restrict__ Wt1, const float* __restrict__ lbias,
            const __nv_bfloat16* __restrict__ Wt2,
            float* __restrict__ out) {
    extern __shared__ char smem[];
    uint32_t sb = smem_u32(smem);
    int tid = threadIdx.x;

    // both B matrices loaded ONCE
    {
        const uint4* B1h = (const uint4*)Wt1;
        const uint4* B1l = (const uint4*)(Wt1 + 16384);
        const uint4* B2h = (const uint4*)Wt2;
        const uint4* B2l = (const uint4*)(Wt2 + 16384);
        #pragma unroll
        for (int i = tid; i < 2048; i += 512) {
            int n = i >> 4, kq = i & 15;
            uint32_t off = n * 272 + kq * 16;
            *(uint4*)(smem + FB1_HI + off) = B1h[i];
            *(uint4*)(smem + FB1_LO + off) = B1l[i];
            *(uint4*)(smem + FB2_HI + off) = B2h[i];
            *(uint4*)(smem + FB2_LO + off) = B2l[i];
        }
    }

    int wid = tid >> 5, lane = tid & 31;
    int m0 = (wid & 3) * 32, n0 = (wid >> 2) * 32;
    int g = lane >> 3, r = lane & 7;
    uint32_t aoff0 = (uint32_t)((m0 + (g & 1) * 8 + r) * 272 + (g >> 1) * 16);
    uint32_t boff0 = (uint32_t)((n0 + (g >> 1) * 8 + r) * 272 + (g & 1) * 16);
    int cr = lane >> 2, cc = (lane & 3) * 2;

    for (int tile = blockIdx.x; tile < FTILES; tile += FGRID) {
        // ---- A-load: fused down_attn gather, 128 rows ----
        #pragma unroll
        for (int i = tid; i < 4096; i += 512) {
            int row = i >> 5, c4 = i & 31;
            int vv = tile * 128 + row;
            int l = vv & (LL - 1);
            float4 b4 = ((const float4*)dbias)[c4];
            float4 xu = ((const float4*)xup)[(size_t)vv * 32 + c4];
            float4 v;
            if (l == 0) {
                v.x = fmaxf(b4.x, 0.f) + xu.x;
                v.y = fmaxf(b4.y, 0.f) + xu.y;
                v.z = fmaxf(b4.z, 0.f) + xu.z;
                v.w = fmaxf(b4.w, 0.f) + xu.w;
            } else {
                int p = vv - l + ((l - 1) >> 1);
                float4 cp = ((const float4*)gC)[(size_t)p * 32 + c4];
                v.x = fmaxf(cp.x + b4.x, 0.f) + xu.x;
                v.y = fmaxf(cp.y + b4.y, 0.f) + xu.y;
                v.z = fmaxf(cp.z + b4.z, 0.f) + xu.z;
                v.w = fmaxf(cp.w + b4.w, 0.f) + xu.w;
            }
            float f[4] = {v.x, v.y, v.z, v.w};
            union { uint2 u; __nv_bfloat16 h[4]; } ph, pl;
            #pragma unroll
            for (int e = 0; e < 4; e++) {
                __nv_bfloat16 hb = __float2bfloat16(f[e]);
                ph.h[e] = hb;
                pl.h[e] = __float2bfloat16(f[e] - __bfloat162float(hb));
            }
            uint32_t off = row * 272 + c4 * 8;
            *(uint2*)(smem + FA_HI + off) = ph.u;
            *(uint2*)(smem + FA_LO + off) = pl.u;
        }
        __syncthreads();

        float acc[2][4][4];
        #pragma unroll
        for (int a = 0; a < 2; a++)
            #pragma unroll
            for (int b = 0; b < 4; b++)
                #pragma unroll
                for (int c = 0; c < 4; c++) acc[a][b][c] = 0.f;

        // ---- mainloop 1: lin GEMM (B1) ----
        #pragma unroll 4
        for (int k16 = 0; k16 < 8; k16++) {
            uint32_t ah[2][4], al[2][4], bh[4][2];
            ldsm_x4(ah[0], sb + FA_HI + aoff0 + k16 * 32);
            ldsm_x4(ah[1], sb + FA_HI + aoff0 + 16 * 272 + k16 * 32);
            ldsm_x4(al[0], sb + FA_LO + aoff0 + k16 * 32);
            ldsm_x4(al[1], sb + FA_LO + aoff0 + 16 * 272 + k16 * 32);
            ldsm_x4(&bh[0][0], sb + FB1_HI + boff0 + k16 * 32);
            ldsm_x4(&bh[2][0], sb + FB1_HI + boff0 + 16 * 272 + k16 * 32);
            #pragma unroll
            for (int mf = 0; mf < 2; mf++)
                #pragma unroll
                for (int nf = 0; nf < 4; nf++)
                    mma16816(acc[mf][nf], ah[mf], bh[nf]);
            #pragma unroll
            for (int mf = 0; mf < 2; mf++)
                #pragma unroll
                for (int nf = 0; nf < 4; nf++)
                    mma16816(acc[mf][nf], al[mf], bh[nf]);
        }
        #pragma unroll 4
        for (int k16 = 0; k16 < 8; k16++) {
            uint32_t ah[2][4], bl[4][2];
            ldsm_x4(ah[0], sb + FA_HI + aoff0 + k16 * 32);
            ldsm_x4(ah[1], sb + FA_HI + aoff0 + 16 * 272 + k16 * 32);
            ldsm_x4(&bl[0][0], sb + FB1_LO + boff0 + k16 * 32);
            ldsm_x4(&bl[2][0], sb + FB1_LO + boff0 + 16 * 272 + k16 * 32);
            #pragma unroll
            for (int mf = 0; mf < 2; mf++)
                #pragma unroll
                for (int nf = 0; nf < 4; nf++)
                    mma16816(acc[mf][nf], ah[mf], bl[nf]);
        }
        __syncthreads();   // all warps done reading A planes

        // ---- write T = relu(acc + lbias) back into A planes (bf16 hi/lo) ----
        #pragma unroll
        for (int mf = 0; mf < 2; mf++) {
            #pragma unroll
            for (int nf = 0; nf < 4; nf++) {
                int col = n0 + nf * 8 + cc;
                float bx = lbias[col], by = lbias[col + 1];
                #pragma unroll
                for (int j = 0; j < 2; j++) {
                    int row = m0 + mf * 16 + cr + j * 8;
                    float f0 = fmaxf(acc[mf][nf][2 * j + 0] + bx, 0.f);
                    float f1 = fmaxf(acc[mf][nf][2 * j + 1] + by, 0.f);
                    union { uint32_t u; __nv_bfloat16 h[2]; } uh, ul;
                    uh.h[0] = __float2bfloat16(f0);
                    uh.h[1] = __float2bfloat16(f1);
                    ul.h[0] = __float2bfloat16(f0 - __bfloat162float(uh.h[0]));
                    ul.h[1] = __float2bfloat16(f1 - __bfloat162float(uh.h[1]));
                    uint32_t off = row * 272 + col * 2;
                    *(uint32_t*)(smem + FA_HI + off) = uh.u;
                    *(uint32_t*)(smem + FA_LO + off) = ul.u;
                }
            }
        }
        __syncthreads();   // T visible to all warps

        #pragma unroll
        for (int a = 0; a < 2; a++)
            #pragma unroll
            for (int b = 0; b < 4; b++)
                #pragma unroll
                for (int c = 0; c < 4; c++) acc[a][b][c] = 0.f;

        // ---- mainloop 2: down GEMM (B2) ----
        #pragma unroll 4
        for (int k16 = 0; k16 < 8; k16++) {
            uint32_t ah[2][4], al[2][4], bh[4][2];
            ldsm_x4(ah[0], sb + FA_HI + aoff0 + k16 * 32);
            ldsm_x4(ah[1], sb + FA_HI + aoff0 + 16 * 272 + k16 * 32);
            ldsm_x4(al[0], sb + FA_LO + aoff0 + k16 * 32);
            ldsm_x4(al[1], sb + FA_LO + aoff0 + 16 * 272 + k16 * 32);
            ldsm_x4(&bh[0][0], sb + FB2_HI + boff0 + k16 * 32);
            ldsm_x4(&bh[2][0], sb + FB2_HI + boff0 + 16 * 272 + k16 * 32);
            #pragma unroll
            for (int mf = 0; mf < 2; mf++)
                #pragma unroll
                for (int nf = 0; nf < 4; nf++)
                    mma16816(acc[mf][nf], ah[mf], bh[nf]);
            #pragma unroll
            for (int mf = 0; mf < 2; mf++)
                #pragma unroll
                for (int nf = 0; nf < 4; nf++)
                    mma16816(acc[mf][nf], al[mf], bh[nf]);
        }
        #pragma unroll 4
        for (int k16 = 0; k16 < 8; k16++) {
            uint32_t ah[2][4], bl[4][2];
            ldsm_x4(ah[0], sb + FA_HI + aoff0 + k16 * 32);
            ldsm_x4(ah[1], sb + FA_HI + aoff0 + 16 * 272 + k16 * 32);
            ldsm_x4(&bl[0][0], sb + FB2_LO + boff0 + k16 * 32);
            ldsm_x4(&bl[2][0], sb + FB2_LO + boff0 + 16 * 272 + k16 * 32);
            #pragma unroll
            for (int mf = 0; mf < 2; mf++)
                #pragma unroll
                for (int nf = 0; nf < 4; nf++)
                    mma16816(acc[mf][nf], ah[mf], bl[nf]);
        }

        // ---- epilogue: pre-activation down output to global ----
        size_t rbase = (size_t)tile * 128;
        #pragma unroll
        for (int mf = 0; mf < 2; mf++) {
            #pragma unroll
            for (int nf = 0; nf < 4; nf++) {
                int col = n0 + nf * 8 + cc;
                int row0 = m0 + mf * 16 + cr;
                *(float2*)(out + (rbase + row0) * 128 + col) =
                    make_float2(acc[mf][nf][0], acc[mf][nf][1]);
                *(float2*)(out + (rbase + row0 + 8) * 128 + col) =
                    make_float2(acc[mf][nf][2], acc[mf][nf][3]);
            }
        }
        __syncthreads();   // protect A planes before next tile's store
    }
}

// ---------------- tiny precompute: w_e = We @ a_e per up layer, W0 dots ----
__global__ void precompute_k(const float* __restrict__ up_We,
                             const float* __restrict__ up_ae,
                             const float* __restrict__ up_W0,
                             const float* __restrict__ as0,
                             const float* __restrict__ ad0) {
    int lane = threadIdx.x;
    for (int i = 0; i < 3; i++) {
        for (int d = 0; d < 4; d++) {
            float s = 0.f;
            for (int t = lane; t < HH; t += 32)
                s += up_We[(i * 4 + d) * HH + t] * up_ae[i * HH + t];
            s = warpsum(s);
            if (lane == 0) g_pre[i * 4 + d] = s;
        }
    }
    float s = 0.f;
    for (int t = lane; t < HH; t += 32) s += up_W0[t] * as0[t];
    s = warpsum(s);
    if (lane == 0) g_pre[12] = s;
    s = 0.f;
    for (int t = lane; t < HH; t += 32) s += up_W0[t] * ad0[t];
    s = warpsum(s);
    if (lane == 0) g_pre[13] = s;
}

// ---------------- up layer 0: W0 is (1,H) -> scalar attn, warp per node ----
__global__ void up0_k(const float* __restrict__ x, const float* __restrict__ W0,
                      const float* __restrict__ bias,
                      const float* __restrict__ edge_attr,
                      float* __restrict__ out) {
    int w = threadIdx.x >> 5, lane = threadIdx.x & 31;
    int v = blockIdx.x * 8 + w;
    int l = v & (LL - 1), bi = v >> LOG2L;
    float xv = x[v];
    int nc = (l < 1023) ? 2 : ((l == 1023) ? 1 : 0);
    float comb;
    if (nc == 0) {
        comb = xv;
    } else {
        float was = g_pre[12], wad = g_pre[13];
        float we0 = g_pre[0], we1 = g_pre[1], we2 = g_pre[2], we3 = g_pre[3];
        int c1 = v + l + 1;
        float x1 = x[c1];
        float x2 = (nc == 2) ? x[c1 + 1] : 0.f;
        long e1 = (long)bi * 2047 + 2 * l;
        const float* ea1 = edge_attr + e1 * 4;
        float e1s = ea1[0] * we0 + ea1[1] * we1 + ea1[2] * we2 + ea1[3] * we3;
        float e2s = 0.f;
        if (nc == 2) {
            const float* ea2 = ea1 + 4;
            e2s = ea2[0] * we0 + ea2[1] * we1 + ea2[2] * we2 + ea2[3] * we3;
        }
        float adv = xv * wad;
        float s1 = lrelu(x1 * was + adv + e1s);
        float s2 = (nc == 2) ? lrelu(x2 * was + adv + e2s) : -1e30f;
        float emean = (nc == 2) ? 0.5f * (e1s + e2s) : e1s;
        float ss = lrelu(xv * was + adv + emean);
        float m = fmaxf(ss, fmaxf(s1, s2));
        float w1 = __expf(s1 - m);
        float w2 = (nc == 2) ? __expf(s2 - m) : 0.f;
        float ws = __expf(ss - m);
        comb = (w1 * x1 + w2 * x2 + ws * xv) / (w1 + w2 + ws);
    }
    float4 w0 = ((const float4*)W0)[lane];
    float4 b4 = ((const float4*)bias)[lane];
    float4 o;
    o.x = fmaxf(comb * w0.x + b4.x, 0.f);
    o.y = fmaxf(comb * w0.y + b4.y, 0.f);
    o.z = fmaxf(comb * w0.z + b4.z, 0.f);
    o.w = fmaxf(comb * w0.w + b4.w, 0.f);
    ((float4*)(out + (size_t)v * HH))[lane] = o;
}

// ---------------- up attention (standalone): warp per node -----------------
__global__ void up_attn_k(const float* __restrict__ h, const float* __restrict__ a_s,
                          const float* __restrict__ a_d,
                          const float* __restrict__ edge_attr, int layer,
                          const float* __restrict__ bias, float* __restrict__ out) {
    int w = threadIdx.x >> 5, lane = threadIdx.x & 31;
    int v = blockIdx.x * 8 + w;
    int l = v & (LL - 1), bi = v >> LOG2L;
    const float4* H = (const float4*)h;
    float4 hv = H[(size_t)v * 32 + lane];
    float4 b4 = ((const float4*)bias)[lane];
    int nc = (l < 1023) ? 2 : ((l == 1023) ? 1 : 0);
    float4* O = (float4*)(out + (size_t)v * HH);
    if (nc == 0) {
        float4 o;
        o.x = fmaxf(hv.x + b4.x, 0.f); o.y = fmaxf(hv.y + b4.y, 0.f);
        o.z = fmaxf(hv.z + b4.z, 0.f); o.w = fmaxf(hv.w + b4.w, 0.f);
        O[lane] = o;
        return;
    }
    int c1 = v + l + 1;
    float4 h1 = H[(size_t)c1 * 32 + lane];
    float4 h2 = (nc == 2) ? H[(size_t)(c1 + 1) * 32 + lane] : make_float4(0, 0, 0, 0);
    float4 as4 = ((const float4*)a_s)[lane];
    float4 ad4 = ((const float4*)a_d)[lane];
    float A1 = warpsum(dot4(h1, as4));
    float A2 = warpsum(dot4(h2, as4));
    float AV = warpsum(dot4(hv, as4));
    float DV = warpsum(dot4(hv, ad4));

    const float* we = g_pre + layer * 4;
    long e1 = (long)bi * 2047 + 2 * l;
    const float* ea1 = edge_attr + e1 * 4;
    float e1s = ea1[0] * we[0] + ea1[1] * we[1] + ea1[2] * we[2] + ea1[3] * we[3];
    float e2s = 0.f;
    if (nc == 2) {
        const float* ea2 = ea1 + 4;
        e2s = ea2[0] * we[0] + ea2[1] * we[1] + ea2[2] * we[2] + ea2[3] * we[3];
    }
    float s1 = lrelu(A1 + DV + e1s);
    float s2 = (nc == 2) ? lrelu(A2 + DV + e2s) : -1e30f;
    float emean = (nc == 2) ? 0.5f * (e1s + e2s) : e1s;
    float ss = lrelu(AV + DV + emean);
    float m = fmaxf(ss, fmaxf(s1, s2));
    float w1 = __expf(s1 - m);
    float w2 = (nc == 2) ? __expf(s2 - m) : 0.f;
    float ws = __expf(ss - m);
    float inv = 1.f / (w1 + w2 + ws);
    float4 o;
    o.x = fmaxf((w1 * h1.x + w2 * h2.x + ws * hv.x) * inv + b4.x, 0.f);
    o.y = fmaxf((w1 * h1.y + w2 * h2.y + ws * hv.y) * inv + b4.y, 0.f);
    o.z = fmaxf((w1 * h1.z + w2 * h2.z + ws * hv.z) * inv + b4.z, 0.f);
    o.w = fmaxf((w1 * h1.w + w2 * h2.w + ws * hv.w) * inv + b4.w, 0.f);
    O[lane] = o;
}

// ------- last down_attn fused with final dot: warp per node ---------------
__global__ void down_final_k(const float* __restrict__ h, const float* __restrict__ bias,
                             const float* __restrict__ x_up, const float* __restrict__ wlast,
                             float* __restrict__ emb, float* __restrict__ dotv) {
    int w = threadIdx.x >> 5, lane = threadIdx.x & 31;
    int v = blockIdx.x * 8 + w;
    int l = v & (LL - 1);
    float4 xu = ((const float4*)x_up)[(size_t)v * 32 + lane];
    float4 b4 = ((const float4*)bias)[lane];
    float4 val;
    if (l == 0) val = b4;
    else {
        int p = v - l + ((l - 1) >> 1);
        float4 hp = ((const float4*)h)[(size_t)p * 32 + lane];
        val.x = hp.x + b4.x; val.y = hp.y + b4.y;
        val.z = hp.z + b4.z; val.w = hp.w + b4.w;
    }
    float4 o;
    o.x = fmaxf(val.x, 0.f) + xu.x;
    o.y = fmaxf(val.y, 0.f) + xu.y;
    o.z = fmaxf(val.z, 0.f) + xu.z;
    o.w = fmaxf(val.w, 0.f) + xu.w;
    ((float4*)(emb + (size_t)v * HH))[lane] = o;
    float4 w4 = ((const float4*)wlast)[lane];
    float q = warpsum(dot4(o, w4));
    if (lane == 0) dotv[v] = q;
}

// ---------------- out[v] = dotv[v] - dotv[root(v)] -------------------------
__global__ void sub_k(const float* __restrict__ dotv, float* __restrict__ out) {
    int v = blockIdx.x * 256 + threadIdx.x;
    out[v] = dotv[v] - dotv[v & ~(LL - 1)];
}

// ---------------------------------------------------------------------------
extern "C" void kernel_launch(void* const* d_in, const int* in_sizes, int n_in,
                              void* d_out, int out_size) {
    const float* x         = (const float*)d_in[0];
    const float* edge_attr = (const float*)d_in[3];
    const float* up_W0     = (const float*)d_in[4];
    const float* up_W      = (const float*)d_in[5];
    const float* up_as     = (const float*)d_in[6];
    const float* up_ad     = (const float*)d_in[7];
    const float* up_We     = (const float*)d_in[8];
    const float* up_ae     = (const float*)d_in[9];
    const float* up_b      = (const float*)d_in[10];
    const float* down_W    = (const float*)d_in[11];
    const float* down_b    = (const float*)d_in[16];
    const float* lin_W     = (const float*)d_in[17];
    const float* lin_b     = (const float*)d_in[18];
    const float* lin_lW    = (const float*)d_in[19];

    float *bufA, *bufB, *bufC, *bufD;
    __nv_bfloat16* wt;
    cudaGetSymbolAddress((void**)&bufA, g_bufA);
    cudaGetSymbolAddress((void**)&bufB, g_bufB);
    cudaGetSymbolAddress((void**)&bufC, g_bufC);
    cudaGetSymbolAddress((void**)&bufD, g_bufD);
    cudaGetSymbolAddress((void**)&wt, g_wt);

    cudaFuncSetAttribute(gemm_hmma, cudaFuncAttributeMaxDynamicSharedMemorySize,
                         SMEM_GEMM);
    cudaFuncSetAttribute(gemm_fused2, cudaFuncAttributeMaxDynamicSharedMemorySize,
                         SMEM_FUSED);

    float* out = (float*)d_out;
    float* emb = out + NN;   // output tuple: (out[B*L], emb[B*L*H]) concatenated

    // mats: 0,1 = up_W[0..1]; 2,3 = down_W[0..1]; 4,5 = lin_W[0..1]
    #define WT(m) (wt + (m) * 2 * 16384)

    precompute_k<<<1, 32>>>(up_We, up_ae, up_W0, up_as, up_ad);
    wconv_k<<<768, 128>>>(up_W, down_W, lin_W);

    // --- up layer 0 (W0 is 1x128: fully scalar attention) ---
    up0_k<<<NN / 8, 256>>>(x, up_W0, up_b, edge_attr, bufB);

    // --- up layer 1 ---
    gemm_hmma<<<GEMM_GRID, 256, SMEM_GEMM>>>(bufB, WT(0), bufC);
    up_attn_k<<<NN / 8, 256>>>(bufC, up_as + HH, up_ad + HH, edge_attr, 1, up_b + HH, bufB);

    // --- up layer 2 -> x_up (bufA) ---
    gemm_hmma<<<GEMM_GRID, 256, SMEM_GEMM>>>(bufB, WT(1), bufC);
    up_attn_k<<<NN / 8, 256>>>(bufC, up_as + 2 * HH, up_ad + 2 * HH, edge_attr, 2,
                               up_b + 2 * HH, bufA);

    // --- down 0 GEMM: C0 = x_up @ down_W0 ---
    gemm_hmma<<<GEMM_GRID, 256, SMEM_GEMM>>>(bufA, WT(2), bufC);

    // --- loop i=0 fused: bufD = [relu(gather(bufC))+xup] @linW0 relu @downW0
    gemm_fused2<<<FGRID, 512, SMEM_FUSED>>>(bufC, bufA, down_b,
                                            WT(4), lin_b, WT(2), bufD);
    // --- loop i=1 fused: bufC = [relu(gather(bufD))+xup] @linW1 relu @downW1
    gemm_fused2<<<FGRID, 512, SMEM_FUSED>>>(bufD, bufA, down_b,
                                            WT(5), lin_b + HH, WT(3), bufC);

    // --- last down_attn fused with final dot (emb into d_out, dotv in bufB) ---
    down_final_k<<<NN / 8, 256>>>(bufC, down_b + HH, bufA, lin_lW, emb, bufB);

    // --- out[v] = dotv[v] - dotv[root] ---
    sub_k<<<NN / 256, 256>>>(bufB, out);
}